// round 1
// baseline (speedup 1.0000x reference)
#include <cuda_runtime.h>

#define NB 256
#define NQ 1000
#define NC 80
#define NN 80000          // NQ * NC per batch
#define TOPK 300
#define NT 1024
#define GSIZE 4096        // elements per group (4 per thread via float4)
#define NGROUPS 20        // 20 * 4096 = 81920 >= 80000
#define CAP 6144          // candidate buffer entries (u64)
#define LISTCAP 2048
#define HBINS 2048
#define TSEL 384          // selection target rank (slack over 300 for ulp safety)

// ---------- monotone float<->uint mapping (handles negatives) ----------
__device__ __forceinline__ unsigned flipf(unsigned b) {
    return (b & 0x80000000u) ? ~b : (b | 0x80000000u);
}
__device__ __forceinline__ unsigned unflipf(unsigned u) {
    return (u & 0x80000000u) ? (u & 0x7FFFFFFFu) : ~u;
}

// ---------- sigmoid matching XLA: logistic(x) = 0.5 + 0.5*tanh(0.5*x),
// tanh via EmitFastTanh (Eigen rational approx, clamp +-9, linear < 4e-4) ----------
__device__ __forceinline__ float sigmoid_ref(float x) {
    float hx = __fmul_rn(0.5f, x);
    float ax = fabsf(hx);
    float xc = fminf(fmaxf(hx, -9.0f), 9.0f);
    float x2 = __fmul_rn(xc, xc);
    float p = -2.76076847742355e-16f;
    p = fmaf(x2, p, 2.00018790482477e-13f);
    p = fmaf(x2, p, -8.60467152213735e-11f);
    p = fmaf(x2, p, 5.12229709037114e-08f);
    p = fmaf(x2, p, 1.48572235717979e-05f);
    p = fmaf(x2, p, 6.37261928875436e-04f);
    p = fmaf(x2, p, 4.89352455891786e-03f);
    p = __fmul_rn(xc, p);
    float q = 1.19825839466702e-06f;
    q = fmaf(x2, q, 1.18534705686654e-04f);
    q = fmaf(x2, q, 2.26843463243900e-03f);
    q = fmaf(x2, q, 4.89352518554385e-03f);
    float t = __fdiv_rn(p, q);
    t = (ax < 4e-4f) ? hx : t;
    return __fadd_rn(__fmul_rn(0.5f, t), 0.5f);
}

// ---------- histogram radix-select over candidate buffer ----------
// keys: (u_logit << 32) | flat_idx. Selects all candidates with logit-bits above
// a bin edge chosen so that >= target survive. Gathers survivors into lst.
// sc[0]=B, sc[1]=B2, sc[2]=refined, sc[3]=gathered count, sc[4]=nAbove
__device__ void run_select(unsigned long long* buf, unsigned long long* lst,
                           unsigned* hist, int* sc, int n, int target) {
    const int tid = threadIdx.x;
    if (n <= target) {
        if (tid == 0) { sc[0] = 0; sc[1] = 0; sc[2] = 0; sc[3] = n; }
        __syncthreads();
        for (int i = tid; i < n; i += NT) lst[i] = buf[i];
        __syncthreads();
        return;
    }
    // level-1: 2048 bins on top 11 bits of flipped-logit
    for (int i = tid; i < HBINS; i += NT) hist[i] = 0;
    __syncthreads();
    for (int i = tid; i < n; i += NT)
        atomicAdd(&hist[(unsigned)(buf[i] >> 53)], 1u);
    __syncthreads();
    for (int off = 1; off < HBINS; off <<= 1) {      // suffix scan
        unsigned v0 = (tid + off < HBINS) ? hist[tid + off] : 0u;
        unsigned v1 = (tid + NT + off < HBINS) ? hist[tid + NT + off] : 0u;
        __syncthreads();
        hist[tid] += v0;
        hist[tid + NT] += v1;
        __syncthreads();
    }
    for (int i = tid; i < HBINS; i += NT) {          // largest bin with suffix>=target
        unsigned s = hist[i];
        unsigned sn = (i + 1 < HBINS) ? hist[i + 1] : 0u;
        if (s >= (unsigned)target && sn < (unsigned)target) {
            sc[0] = i; sc[4] = (int)sn;
        }
    }
    if (tid == 0) { sc[2] = 0; sc[3] = 0; }
    __syncthreads();
    const int B = sc[0];
    const int nAbove = sc[4];
    const int selcount = (int)hist[B];
    int refined = 0, B2 = 0;
    if (selcount > 1024) {                            // level-2 refine within bin B
        __syncthreads();
        for (int i = tid; i < HBINS; i += NT) hist[i] = 0;
        __syncthreads();
        for (int i = tid; i < n; i += NT) {
            unsigned long long k = buf[i];
            if ((unsigned)(k >> 53) == (unsigned)B)
                atomicAdd(&hist[(unsigned)(k >> 42) & 0x7FFu], 1u);
        }
        __syncthreads();
        for (int off = 1; off < HBINS; off <<= 1) {
            unsigned v0 = (tid + off < HBINS) ? hist[tid + off] : 0u;
            unsigned v1 = (tid + NT + off < HBINS) ? hist[tid + NT + off] : 0u;
            __syncthreads();
            hist[tid] += v0;
            hist[tid + NT] += v1;
            __syncthreads();
        }
        int extra = target - nAbove;
        for (int i = tid; i < HBINS; i += NT) {
            unsigned s = hist[i];
            unsigned sn = (i + 1 < HBINS) ? hist[i + 1] : 0u;
            if (s >= (unsigned)extra && sn < (unsigned)extra) sc[1] = i;
        }
        if (tid == 0) sc[2] = 1;
        __syncthreads();
        refined = 1;
        B2 = sc[1];
    }
    // gather survivors
    for (int i = tid; i < n; i += NT) {
        unsigned long long k = buf[i];
        unsigned bin = (unsigned)(k >> 53);
        bool sel = (bin > (unsigned)B) ||
                   (bin == (unsigned)B &&
                    (!refined || (((unsigned)(k >> 42) & 0x7FFu) >= (unsigned)B2)));
        if (sel) {
            int p = atomicAdd(&sc[3], 1);
            if (p < LISTCAP) lst[p] = k;
        }
    }
    __syncthreads();
}

extern "C" __global__ void __launch_bounds__(NT)
postproc_kernel(const float* __restrict__ logits,
                const float* __restrict__ boxes,
                float* __restrict__ out) {
    extern __shared__ unsigned char smem_raw[];
    unsigned long long* buf = reinterpret_cast<unsigned long long*>(smem_raw);
    unsigned long long* lst = buf + CAP;
    unsigned* hist = reinterpret_cast<unsigned*>(lst + LISTCAP);
    __shared__ int s_count;
    __shared__ unsigned s_thr;
    __shared__ int sc[5];

    const int tid = threadIdx.x;
    const int b = blockIdx.x;
    const float* Lp = logits + (size_t)b * NN;

    if (tid == 0) { s_count = 0; s_thr = 0u; }
    __syncthreads();

    // ---------------- streaming pass: one read of logits ----------------
    for (int g = 0; g < NGROUPS; ++g) {
        int base = g * GSIZE + tid * 4;
        if (base < NN) {               // NN % 4 == 0 -> whole float4 valid
            float4 v = *reinterpret_cast<const float4*>(Lp + base);
            unsigned thr = s_thr;
            unsigned ub0 = flipf(__float_as_uint(v.x));
            unsigned ub1 = flipf(__float_as_uint(v.y));
            unsigned ub2 = flipf(__float_as_uint(v.z));
            unsigned ub3 = flipf(__float_as_uint(v.w));
            unsigned ubs[4] = {ub0, ub1, ub2, ub3};
            #pragma unroll
            for (int e = 0; e < 4; ++e) {
                if (ubs[e] >= thr) {    // warp-aggregated append
                    unsigned long long key =
                        ((unsigned long long)ubs[e] << 32) | (unsigned)(base + e);
                    unsigned mask = __activemask();
                    int lane = tid & 31;
                    int leader = __ffs(mask) - 1;
                    int pos = 0;
                    if (lane == leader) pos = atomicAdd(&s_count, __popc(mask));
                    pos = __shfl_sync(mask, pos, leader) +
                          __popc(mask & ((1u << lane) - 1u));
                    if (pos < CAP) buf[pos] = key;
                }
            }
        }
        __syncthreads();
        if (g == 0 || s_count > CAP - GSIZE) {     // establish / raise threshold
            int n = min(s_count, CAP);
            run_select(buf, lst, hist, sc, n, TSEL);
            int m = min(sc[3], LISTCAP);
            for (int i = tid; i < m; i += NT) buf[i] = lst[i];
            __syncthreads();
            if (tid == 0) {
                s_count = m;
                s_thr = sc[2] ? (((unsigned)sc[0] << 21) | ((unsigned)sc[1] << 10))
                              : ((unsigned)sc[0] << 21);
            }
            __syncthreads();
        }
    }

    // ---------------- final exact top-K ----------------
    int n = min(s_count, CAP);
    run_select(buf, lst, hist, sc, n, TSEL);
    int m = min(sc[3], LISTCAP);

    // convert survivors to sigmoid rank keys: score desc, index asc on ties
    for (int i = tid; i < m; i += NT) {
        unsigned long long k = lst[i];
        unsigned u = (unsigned)(k >> 32);
        unsigned idx = (unsigned)k;
        float x = __uint_as_float(unflipf(u));
        float s = sigmoid_ref(x);
        lst[i] = ((unsigned long long)__float_as_uint(s) << 32) |
                 (unsigned)(0xFFFFFFFFu - idx);
    }
    __syncthreads();

    // rank by counting (keys unique); write outputs for rank < TOPK
    for (int i = tid; i < m; i += NT) {
        unsigned long long k = lst[i];
        int r = 0;
        for (int j = 0; j < m; ++j) r += (lst[j] > k) ? 1 : 0;
        if (r < TOPK) {
            unsigned idx = 0xFFFFFFFFu - (unsigned)k;
            float s = __uint_as_float((unsigned)(k >> 32));
            int q = (int)(idx / NC);
            int c = (int)(idx - (unsigned)q * NC);
            size_t o = (size_t)b * TOPK + (size_t)r;
            // labels region: [0, NB*TOPK)
            out[o] = (float)c;
            // boxes region: [NB*TOPK, NB*TOPK*5), cxcywh -> xyxy
            float4 bx = *reinterpret_cast<const float4*>(
                boxes + ((size_t)b * NQ + (size_t)q) * 4);
            float4 xy;
            xy.x = bx.x - 0.5f * bx.z;
            xy.y = bx.y - 0.5f * bx.w;
            xy.z = bx.x + 0.5f * bx.z;
            xy.w = bx.y + 0.5f * bx.w;
            *reinterpret_cast<float4*>(out + (size_t)NB * TOPK + o * 4) = xy;
            // scores region: [NB*TOPK*5, NB*TOPK*6)
            out[(size_t)NB * TOPK * 5 + o] = s;
        }
    }
}

extern "C" void kernel_launch(void* const* d_in, const int* in_sizes, int n_in,
                              void* d_out, int out_size) {
    const float* logits = (const float*)d_in[0];
    const float* boxes = (const float*)d_in[1];
    size_t smem = (size_t)CAP * 8 + (size_t)LISTCAP * 8 + (size_t)HBINS * 4; // 73728 B
    cudaFuncSetAttribute(postproc_kernel,
                         cudaFuncAttributeMaxDynamicSharedMemorySize, (int)smem);
    postproc_kernel<<<NB, NT, smem>>>(logits, boxes, (float*)d_out);
}